// round 13
// baseline (speedup 1.0000x reference)
#include <cuda_runtime.h>
#include <cuda_fp16.h>
#include <mma.h>
#include <cstddef>
#include <cstdint>

using namespace nvcuda;

#define BB 64
#define TT 512
#define DD 512
#define HH 768
#define NG 3072
#define MMROWS (BB * TT)
#define NCTA 96
#define NCTA_DIR 48

// recurrence smem layout (bytes)
#define LDH 80                   // Ws row: 80 halves (160 B)
#define ST_LDH 136               // stage row: 128 + 8 pad halves (272 B)
#define ST_OFF 122880            // Ws: 768 x 80 halves
#define ST_B 17408               // stage: 64 x 136 halves
#define NSTAGE 4
#define GS_OFF 192512            // Gs: 64 x 68 fp32
#define GS_LD 68
#define BS_OFF 209920
#define SMEM_REC 210176

__device__ float  g_xp[(size_t)2 * MMROWS * NG];
__device__ __half g_h[2][2][BB * HH];
__device__ unsigned g_bar_count[2];
__device__ unsigned g_bar_gen[2];

__device__ __forceinline__ float sigmoidf(float x) {
    return 1.0f / (1.0f + __expf(-x));
}
__device__ __forceinline__ uint32_t smem_u32(const void* p) {
    uint32_t a;
    asm("{ .reg .u64 t; cvta.to.shared.u64 t, %1; cvt.u32.u64 %0, t; }" : "=r"(a) : "l"(p));
    return a;
}

// split per-direction grid barrier (known-good)
__device__ __forceinline__ unsigned bar_arrive(int dir) {
    unsigned gen = *((volatile unsigned*)&g_bar_gen[dir]);
    __threadfence();
    unsigned arr = atomicAdd(&g_bar_count[dir], 1u);
    if (arr == NCTA_DIR - 1) {
        g_bar_count[dir] = 0;
        __threadfence();
        atomicAdd(&g_bar_gen[dir], 1u);
    }
    return gen;
}
__device__ __forceinline__ void bar_wait(int dir, unsigned gen) {
    int spins = 0;
    while (*((volatile unsigned*)&g_bar_gen[dir]) == gen) {
        if (++spins > 64) __nanosleep(20);
    }
    __threadfence();
}

// ---------------------------------------------------------------------------
// xproj (unchanged, known-good)
// ---------------------------------------------------------------------------
__global__ void __launch_bounds__(256) xproj_kernel(
    const float* __restrict__ seq,
    const float* __restrict__ Wfw,
    const float* __restrict__ Wbw)
{
    const int dir = blockIdx.z;
    const float* W = dir ? Wbw : Wfw;
    float* xp = g_xp + (size_t)dir * MMROWS * NG;
    const int m0 = blockIdx.x * 128;
    const int n0 = blockIdx.y * 64;

    __shared__ __align__(16) float As[128][20];
    __shared__ __align__(16) float Bs[16][68];

    const int tid = threadIdx.x;
    const int w = tid >> 5, wm = w & 3, wn = w >> 2;

    wmma::fragment<wmma::accumulator, 16, 16, 8, float> acc[2][2];
#pragma unroll
    for (int i = 0; i < 2; i++)
#pragma unroll
        for (int j = 0; j < 2; j++) wmma::fill_fragment(acc[i][j], 0.0f);

    float ra[8], rb[4];
#pragma unroll
    for (int e = 0; e < 8; e++) {
        int idx = e * 256 + tid; int r = idx >> 4, c = idx & 15;
        ra[e] = seq[(size_t)(m0 + r) * DD + c];
    }
#pragma unroll
    for (int e = 0; e < 4; e++) {
        int idx = e * 256 + tid; int r = idx >> 6, c = idx & 63;
        rb[e] = W[(size_t)r * NG + n0 + c];
    }

    for (int kt = 0; kt < DD / 16; kt++) {
        __syncthreads();
#pragma unroll
        for (int e = 0; e < 8; e++) {
            int idx = e * 256 + tid; int r = idx >> 4, c = idx & 15;
            As[r][c] = ra[e];
        }
#pragma unroll
        for (int e = 0; e < 4; e++) {
            int idx = e * 256 + tid; int r = idx >> 6, c = idx & 63;
            Bs[r][c] = rb[e];
        }
        __syncthreads();
        if (kt + 1 < DD / 16) {
            int k0 = (kt + 1) * 16;
#pragma unroll
            for (int e = 0; e < 8; e++) {
                int idx = e * 256 + tid; int r = idx >> 4, c = idx & 15;
                ra[e] = seq[(size_t)(m0 + r) * DD + k0 + c];
            }
#pragma unroll
            for (int e = 0; e < 4; e++) {
                int idx = e * 256 + tid; int r = idx >> 6, c = idx & 63;
                rb[e] = W[(size_t)(k0 + r) * NG + n0 + c];
            }
        }
#pragma unroll
        for (int k8 = 0; k8 < 16; k8 += 8) {
            wmma::fragment<wmma::matrix_a, 16, 16, 8, wmma::precision::tf32, wmma::row_major> af[2];
            wmma::fragment<wmma::matrix_b, 16, 16, 8, wmma::precision::tf32, wmma::row_major> bf[2];
#pragma unroll
            for (int fm = 0; fm < 2; fm++) {
                wmma::load_matrix_sync(af[fm], &As[wm * 32 + fm * 16][k8], 20);
#pragma unroll
                for (int i = 0; i < af[fm].num_elements; i++)
                    af[fm].x[i] = wmma::__float_to_tf32(af[fm].x[i]);
            }
#pragma unroll
            for (int fn = 0; fn < 2; fn++) {
                wmma::load_matrix_sync(bf[fn], &Bs[k8][wn * 32 + fn * 16], 68);
#pragma unroll
                for (int i = 0; i < bf[fn].num_elements; i++)
                    bf[fn].x[i] = wmma::__float_to_tf32(bf[fn].x[i]);
            }
#pragma unroll
            for (int fm = 0; fm < 2; fm++)
#pragma unroll
                for (int fn = 0; fn < 2; fn++)
                    wmma::mma_sync(acc[fm][fn], af[fm], bf[fn], acc[fm][fn]);
        }
    }
#pragma unroll
    for (int fm = 0; fm < 2; fm++)
#pragma unroll
        for (int fn = 0; fn < 2; fn++) {
            size_t row = m0 + wm * 32 + fm * 16;
            size_t col = n0 + wn * 32 + fn * 16;
            wmma::store_matrix_sync(xp + row * NG + col, acc[fm][fn], NG,
                                    wmma::mem_row_major);
        }
}

__device__ __forceinline__ void cp16s(uint32_t smem_dst, const void* gmem_src) {
    asm volatile("cp.async.ca.shared.global [%0], [%1], 16;\n"
                 :: "r"(smem_dst), "l"(gmem_src));
}

// ---------------------------------------------------------------------------
// Persistent recurrence: fp16 WMMA, chunk K=128, 6 iters/step, 4 stages,
// dual accumulator for MMA ILP, dual-sync per chunk, 4x4 warp tiling.
// ---------------------------------------------------------------------------
__global__ void __launch_bounds__(512, 1) lstm_persistent(
    const int* __restrict__ seq_len,
    const float* __restrict__ Wfw, const float* __restrict__ bfw,
    const float* __restrict__ Wbw, const float* __restrict__ bbw,
    float* __restrict__ out)
{
    const int dir = blockIdx.x / 48;
    const int jb  = blockIdx.x % 48;
    const float* W    = dir ? Wbw : Wfw;
    const float* bias = dir ? bbw : bfw;
    const float* xp = g_xp + (size_t)dir * MMROWS * NG;

    extern __shared__ __align__(128) char sm[];
    const uint32_t smb = smem_u32(sm);
    __half* Ws = (__half*)sm;                       // [768][LDH]
    float*  Gs = (float*)(sm + GS_OFF);             // [64][GS_LD]
    float*  bs = (float*)(sm + BS_OFF);             // 64 floats
    __shared__ unsigned s_gen;

    const int tid = threadIdx.x;
    const int w  = tid >> 5;
    const int wm = w & 3;      // 16-row (batch) block
    const int wn = w >> 2;     // 16-col (gate) block

    // one-time: W slice -> fp16 smem
    for (int i = tid; i < 768 * 64; i += 512) {
        int k = i >> 6, n = i & 63;
        int g = n >> 4, c = n & 15;
        Ws[k * LDH + n] = __float2half(W[(size_t)(DD + k) * NG + g * HH + jb * 16 + c]);
    }
    if (tid < 64) {
        int g = tid >> 4, c = tid & 15;
        bs[tid] = bias[g * HH + jb * 16 + c];
    }

    // per-thread cell ownership
    const int j  = tid & 15;
    const int jg = jb * 16 + j;
    const int bb0 = tid >> 4;
    const int bb1 = bb0 + 32;
    const int L0 = seq_len[bb0];
    const int L1 = seq_len[bb1];
    float c0 = 0.f, c1 = 0.f, h0 = 0.f, h1 = 0.f;
    g_h[dir][0][bb0 * HH + jg] = __float2half(0.f);
    g_h[dir][0][bb1 * HH + jg] = __float2half(0.f);

    // chunk copy mapping: 64 rows x 256B = 1024 x 16B units; 2 per thread
    // unit u: row = u>>4, col16 = u&15
    const int u0 = tid, u1 = tid + 512;
    const uint32_t cd0 = smb + ST_OFF + (uint32_t)((u0 >> 4) * (ST_LDH * 2) + (u0 & 15) * 16);
    const uint32_t cd1 = smb + ST_OFF + (uint32_t)((u1 >> 4) * (ST_LDH * 2) + (u1 & 15) * 16);
    const int cs0 = (u0 >> 4) * HH + (u0 & 15) * 8;    // halves
    const int cs1 = (u1 >> 4) * HH + (u1 & 15) * 8;

    __syncthreads();
    if (tid == 0) { unsigned g0 = bar_arrive(dir); bar_wait(dir, g0); }
    __syncthreads();

    for (int t = 0; t < TT; t++) {
        const int parr = t & 1;
        const __half* hsrc = g_h[dir][parr];
        __half* hdst = g_h[dir][parr ^ 1];

        const bool a0 = t < L0, a1 = t < L1;
        const int tx0 = dir ? (a0 ? L0 - 1 - t : t) : t;
        const int tx1 = dir ? (a1 ? L1 - 1 - t : t) : t;
        const float* x0 = xp + ((size_t)bb0 * TT + tx0) * NG + jg;
        const float* x1 = xp + ((size_t)bb1 * TT + tx1) * NG + jg;
        float xv00 = x0[0], xv01 = x0[HH], xv02 = x0[2 * HH], xv03 = x0[3 * HH];
        float xv10 = x1[0], xv11 = x1[HH], xv12 = x1[2 * HH], xv13 = x1[3 * HH];

        wmma::fragment<wmma::accumulator, 16, 16, 16, float> accA, accB;
        wmma::fill_fragment(accA, 0.f);
        wmma::fill_fragment(accB, 0.f);

        // prologue: issue chunks 0..3 into stages 0..3
#pragma unroll
        for (int s = 0; s < NSTAGE; s++) {
            cp16s(cd0 + s * ST_B, hsrc + cs0 + s * 128);
            cp16s(cd1 + s * ST_B, hsrc + cs1 + s * 128);
            asm volatile("cp.async.commit_group;\n");
        }

        for (int ck = 0; ck < 6; ck++) {
            if (ck < 3)       asm volatile("cp.async.wait_group 3;\n");
            else if (ck == 3) asm volatile("cp.async.wait_group 2;\n");
            else if (ck == 4) asm volatile("cp.async.wait_group 1;\n");
            else              asm volatile("cp.async.wait_group 0;\n");
            __syncthreads();   // chunk ck visible to all warps

            const __half* Hst = (const __half*)(sm + ST_OFF + (ck & 3) * ST_B);
#pragma unroll
            for (int k16 = 0; k16 < 8; k16++) {
                wmma::fragment<wmma::matrix_a, 16, 16, 16, half, wmma::row_major> af;
                wmma::load_matrix_sync(af, Hst + (wm * 16) * ST_LDH + k16 * 16, ST_LDH);
                wmma::fragment<wmma::matrix_b, 16, 16, 16, half, wmma::row_major> bf;
                wmma::load_matrix_sync(bf, Ws + (ck * 128 + k16 * 16) * LDH + wn * 16, LDH);
                if (k16 & 1) wmma::mma_sync(accB, af, bf, accB);
                else         wmma::mma_sync(accA, af, bf, accA);
            }
            __syncthreads();   // readers of stage ck&3 done

            if (ck + 4 < 6) {  // refill the just-consumed stage
                cp16s(cd0 + (ck & 3) * ST_B, hsrc + cs0 + (ck + 4) * 128);
                cp16s(cd1 + (ck & 3) * ST_B, hsrc + cs1 + (ck + 4) * 128);
                asm volatile("cp.async.commit_group;\n");
            }
        }

        // merge accumulators and stage gates
#pragma unroll
        for (int i = 0; i < accA.num_elements; i++) accA.x[i] += accB.x[i];
        wmma::store_matrix_sync(Gs + (wm * 16) * GS_LD + wn * 16, accA, GS_LD,
                                wmma::mem_row_major);
        __syncthreads();

        // fused cell update (fp32); h stored fp16 before the arrive fence
        float nh0, nh1;
        {
            float gi = Gs[bb0 * GS_LD +  0 + j] + xv00 + bs[j];
            float gj = Gs[bb0 * GS_LD + 16 + j] + xv01 + bs[16 + j];
            float gf = Gs[bb0 * GS_LD + 32 + j] + xv02 + bs[32 + j];
            float go = Gs[bb0 * GS_LD + 48 + j] + xv03 + bs[48 + j];
            float nc = c0 * sigmoidf(gf + 1.f) + sigmoidf(gi) * tanhf(gj);
            nh0 = tanhf(nc) * sigmoidf(go);
            if (a0) { c0 = nc; h0 = nh0; }
            hdst[bb0 * HH + jg] = __float2half(h0);
        }
        {
            float gi = Gs[bb1 * GS_LD +  0 + j] + xv10 + bs[j];
            float gj = Gs[bb1 * GS_LD + 16 + j] + xv11 + bs[16 + j];
            float gf = Gs[bb1 * GS_LD + 32 + j] + xv12 + bs[32 + j];
            float go = Gs[bb1 * GS_LD + 48 + j] + xv13 + bs[48 + j];
            float nc = c1 * sigmoidf(gf + 1.f) + sigmoidf(gi) * tanhf(gj);
            nh1 = tanhf(nc) * sigmoidf(go);
            if (a1) { c1 = nc; h1 = nh1; }
            hdst[bb1 * HH + jg] = __float2half(h1);
        }

        __syncthreads();
        if (tid == 0) s_gen = bar_arrive(dir);   // fence covers h stores only
        {
            int to0 = (dir && a0) ? (L0 - 1 - t) : t;
            out[((size_t)bb0 * TT + to0) * (2 * HH) + dir * HH + jg] = a0 ? nh0 : 0.f;
            int to1 = (dir && a1) ? (L1 - 1 - t) : t;
            out[((size_t)bb1 * TT + to1) * (2 * HH) + dir * HH + jg] = a1 ? nh1 : 0.f;
        }
        if (tid == 0) bar_wait(dir, s_gen);
        __syncthreads();
    }

    out[(size_t)BB * TT * 2 * HH + (size_t)bb0 * 2 * HH + dir * HH + jg] = h0;
    out[(size_t)BB * TT * 2 * HH + (size_t)bb1 * 2 * HH + dir * HH + jg] = h1;
}

// ---------------------------------------------------------------------------
extern "C" void kernel_launch(void* const* d_in, const int* in_sizes, int n_in,
                              void* d_out, int out_size)
{
    const float* seq     = (const float*)d_in[0];
    const int*   seq_len = (const int*)d_in[1];
    const float* Wfw     = (const float*)d_in[2];
    const float* bfw     = (const float*)d_in[3];
    const float* Wbw     = (const float*)d_in[4];
    const float* bbw     = (const float*)d_in[5];
    float* out = (float*)d_out;

    cudaFuncSetAttribute(lstm_persistent,
                         cudaFuncAttributeMaxDynamicSharedMemorySize, SMEM_REC);

    xproj_kernel<<<dim3(MMROWS / 128, NG / 64, 2), 256>>>(seq, Wfw, Wbw);

    lstm_persistent<<<NCTA, 512, SMEM_REC>>>(seq_len, Wfw, bfw, Wbw, bbw, out);
}